// round 5
// baseline (speedup 1.0000x reference)
#include <cuda_runtime.h>
#include <math.h>
#include <stdint.h>

#define B_   8192
#define DIN  1024
#define HID  2048
#define LAT  256
#define KC   4096

typedef unsigned long long ull;

// ---------------- scratch (device globals; no allocation allowed) ----------
__device__ float g_h1[(size_t)B_ * HID];   // 64 MB
__device__ float g_h2[(size_t)B_ * HID];   // 64 MB
__device__ float g_ze[(size_t)B_ * LAT];   // 8 MB
__device__ float g_zq[(size_t)B_ * LAT];   // 8 MB
__device__ float g_zsq[B_];
__device__ float g_esq[KC];
__device__ float g_rowloss[B_];
__device__ int   g_idx[B_];

__device__ __forceinline__ float gelu_exact(float x) {
    return 0.5f * x * (1.0f + erff(x * 0.7071067811865476f));
}

// packed fp32x2 FMA: two independent rn-rounded fp32 FMAs (FFMA2)
__device__ __forceinline__ void fma2(ull& d, ull a, ull b, ull c) {
    asm("fma.rn.f32x2 %0, %1, %2, %3;" : "=l"(d) : "l"(a), "l"(b), "l"(c));
}
__device__ __forceinline__ ull pack2(float lo, float hi) {
    ull r;
    asm("mov.b64 %0, {%1, %2};" : "=l"(r) : "f"(lo), "f"(hi));
    return r;
}
__device__ __forceinline__ void unpack2(ull v, float& lo, float& hi) {
    asm("mov.b64 {%0, %1}, %2;" : "=f"(lo), "=f"(hi) : "l"(v));
}

// ================= EXACT encoder GEMM (FFMA2, BK=16, double-buffered) ======
// Accumulation order per accumulator is k-ascending: bit-identical to the
// Round-2/4 passing kernel. Only data staging changed.
template<bool GELU>
__global__ void __launch_bounds__(256, 2) sgemm_bias_act(
    const float* __restrict__ A, const float* __restrict__ Bm,
    const float* __restrict__ bias, float* __restrict__ C,
    int M, int N, int K)
{
    __shared__ float As[2][16][128];
    __shared__ float Bs[2][16][128];

    const int tid = threadIdx.x;
    const int bm = blockIdx.y * 128;
    const int bn = blockIdx.x * 128;

    const int arow = tid >> 1;            // 0..127
    const int acol = (tid & 1) * 8;       // 0 or 8
    const int brow = tid >> 4;            // 0..15
    const int bcol = (tid & 15) * 8;      // 0..120

    const int ty = tid >> 4;              // 0..15
    const int tx = tid & 15;              // 0..15

    ull acc2[8][4];
#pragma unroll
    for (int i = 0; i < 8; i++)
#pragma unroll
        for (int j = 0; j < 4; j++) acc2[i][j] = 0ull;

    const float* Aptr = A + (size_t)(bm + arow) * K + acol;
    const float* Bptr = Bm + (size_t)brow * N + bn + bcol;

    // fill stage 0
    {
        float4 a0 = *(const float4*)(Aptr);
        float4 a1 = *(const float4*)(Aptr + 4);
        As[0][acol + 0][arow] = a0.x; As[0][acol + 1][arow] = a0.y;
        As[0][acol + 2][arow] = a0.z; As[0][acol + 3][arow] = a0.w;
        As[0][acol + 4][arow] = a1.x; As[0][acol + 5][arow] = a1.y;
        As[0][acol + 6][arow] = a1.z; As[0][acol + 7][arow] = a1.w;
        *(float4*)&Bs[0][brow][bcol]     = *(const float4*)(Bptr);
        *(float4*)&Bs[0][brow][bcol + 4] = *(const float4*)(Bptr + 4);
    }
    __syncthreads();

    const int nt = K / 16;
    for (int ti = 0; ti < nt; ti++) {
        const int cur = ti & 1;
        float4 na0, na1, nb0, nb1;
        const bool more = (ti + 1 < nt);
        if (more) {
            na0 = *(const float4*)(Aptr + (ti + 1) * 16);
            na1 = *(const float4*)(Aptr + (ti + 1) * 16 + 4);
            nb0 = *(const float4*)(Bptr + (size_t)((ti + 1) * 16) * N);
            nb1 = *(const float4*)(Bptr + (size_t)((ti + 1) * 16) * N + 4);
        }

#pragma unroll
        for (int kk = 0; kk < 16; kk++) {
            float ra[8];
            *(float4*)(ra)     = *(const float4*)&As[cur][kk][ty * 8];
            *(float4*)(ra + 4) = *(const float4*)&As[cur][kk][ty * 8 + 4];
            ull rb2[4];
            *(uint4*)&rb2[0] = *(const uint4*)&Bs[cur][kk][tx * 8];
            *(uint4*)&rb2[2] = *(const uint4*)&Bs[cur][kk][tx * 8 + 4];
#pragma unroll
            for (int i = 0; i < 8; i++) {
                ull a2 = pack2(ra[i], ra[i]);
#pragma unroll
                for (int j = 0; j < 4; j++)
                    fma2(acc2[i][j], a2, rb2[j], acc2[i][j]);
            }
        }

        if (more) {
            const int nxt = cur ^ 1;
            As[nxt][acol + 0][arow] = na0.x; As[nxt][acol + 1][arow] = na0.y;
            As[nxt][acol + 2][arow] = na0.z; As[nxt][acol + 3][arow] = na0.w;
            As[nxt][acol + 4][arow] = na1.x; As[nxt][acol + 5][arow] = na1.y;
            As[nxt][acol + 6][arow] = na1.z; As[nxt][acol + 7][arow] = na1.w;
            *(float4*)&Bs[nxt][brow][bcol]     = nb0;
            *(float4*)&Bs[nxt][brow][bcol + 4] = nb1;
        }
        __syncthreads();
    }

#pragma unroll
    for (int i = 0; i < 8; i++) {
        int row = bm + ty * 8 + i;
#pragma unroll
        for (int j = 0; j < 4; j += 2) {
            int col = bn + tx * 8 + j * 2;
            float4 v;
            unpack2(acc2[i][j],     v.x, v.y);
            unpack2(acc2[i][j + 1], v.z, v.w);
            v.x += bias[col + 0];
            v.y += bias[col + 1];
            v.z += bias[col + 2];
            v.w += bias[col + 3];
            if (GELU) {
                v.x = gelu_exact(v.x); v.y = gelu_exact(v.y);
                v.z = gelu_exact(v.z); v.w = gelu_exact(v.w);
            }
            *(float4*)(C + (size_t)row * N + col) = v;
        }
    }
}

// ================= 3xTF32 tensor-core GEMM (decoder only) ==================
// Fragment-major smem layout: consumer fragment loads are LDS.128.
// Double-buffered stages; mma sequence per accumulator unchanged vs Round 4
// (bitwise-identical x_recon).
__device__ __forceinline__ void split_tf32(float x, uint32_t& hi, uint32_t& lo) {
    asm("cvt.rna.tf32.f32 %0, %1;" : "=r"(hi) : "f"(x));
    float r = x - __uint_as_float(hi);
    asm("cvt.rna.tf32.f32 %0, %1;" : "=r"(lo) : "f"(r));
}

__device__ __forceinline__ void mma8(float* d, const uint32_t* a, const uint32_t* b) {
    asm("mma.sync.aligned.m16n8k8.row.col.f32.tf32.tf32.f32 "
        "{%0,%1,%2,%3}, {%4,%5,%6,%7}, {%8,%9}, {%0,%1,%2,%3};"
        : "+f"(d[0]), "+f"(d[1]), "+f"(d[2]), "+f"(d[3])
        : "r"(a[0]), "r"(a[1]), "r"(a[2]), "r"(a[3]), "r"(b[0]), "r"(b[1]));
}

// stage layout (u32 units)
#define AH_OFF 0
#define AL_OFF 4096
#define BH_OFF 8192
#define BL_OFF 12800
#define STAGE_U32 17408
#define SM_BYTES (2 * STAGE_U32 * 4)   // 139264 B

// B lane-chunk rotation so LDS.128 across a warp hits all 32 banks
__device__ __forceinline__ int b_lane_off(int lane) {
    return lane * 8 + ((lane >> 2) << 2);
}

__device__ __forceinline__ void store_A_frag(
    uint32_t* hi_base, uint32_t* lo_base, int ar, int ac4, const float4* pa)
{
#pragma unroll
    for (int i = 0; i < 4; i++) {
        int row = ar + i * 32;
        int t16 = row >> 4;
        int rr  = row & 15;
        int gg  = rr & 7;
        int b0  = rr >> 3;
        float v[4] = { pa[i].x, pa[i].y, pa[i].z, pa[i].w };
#pragma unroll
        for (int j = 0; j < 4; j++) {
            int k  = ac4 + j;
            int k8 = k >> 3, cc = k & 7;
            int tt = cc & 3, b1 = cc >> 2;
            int idx = k8 * 1024 + t16 * 128 + (gg * 4 + tt) * 4 + b0 + 2 * b1;
            uint32_t h, l;
            split_tf32(v[j], h, l);
            hi_base[idx] = h;
            lo_base[idx] = l;
        }
    }
}

__device__ __forceinline__ void store_B_frag(
    uint32_t* hi_base, uint32_t* lo_base, int bk, int bc4, const float4* pb)
{
#pragma unroll
    for (int i = 0; i < 4; i++) {
        int k  = bk + i * 8;
        int k8 = k >> 3, cc = k & 7;
        int tt = cc & 3, b1 = cc >> 2;
        float v[4] = { pb[i].x, pb[i].y, pb[i].z, pb[i].w };
#pragma unroll
        for (int j = 0; j < 4; j++) {
            int col = bc4 + j;
            int wn  = col >> 5;
            int jn  = (col >> 3) & 3;
            int gg  = col & 7;
            int lane = gg * 4 + tt;
            int idx = k8 * 1152 + wn * 288 + b_lane_off(lane) + jn * 2 + b1;
            uint32_t h, l;
            split_tf32(v[j], h, l);
            hi_base[idx] = h;
            lo_base[idx] = l;
        }
    }
}

template<bool GELU>
__global__ void __launch_bounds__(256) mma_gemm_bias_act(
    const float* __restrict__ A, const float* __restrict__ Bm,
    const float* __restrict__ bias, float* __restrict__ C,
    int M, int N, int K)
{
    extern __shared__ uint32_t smu[];

    const int tid  = threadIdx.x;
    const int wid  = tid >> 5;
    const int lane = tid & 31;
    const int g = lane >> 2;
    const int t = lane & 3;
    const int warp_m = wid & 1;
    const int warp_n = wid >> 1;
    const int bm = blockIdx.y * 128;
    const int bn = blockIdx.x * 128;

    float acc[4][4][4];
#pragma unroll
    for (int i = 0; i < 4; i++)
#pragma unroll
        for (int j = 0; j < 4; j++)
#pragma unroll
            for (int r = 0; r < 4; r++) acc[i][j][r] = 0.0f;

    const int ar  = tid >> 3;             // 0..31
    const int ac4 = (tid & 7) * 4;        // 0..28
    const int bk  = tid >> 5;             // 0..7
    const int bc4 = lane * 4;             // 0..124

    // fill stage 0
    {
        float4 pa[4], pb[4];
#pragma unroll
        for (int i = 0; i < 4; i++)
            pa[i] = *(const float4*)&A[(size_t)(bm + ar + i * 32) * K + ac4];
#pragma unroll
        for (int i = 0; i < 4; i++)
            pb[i] = *(const float4*)&Bm[(size_t)(bk + i * 8) * N + bn + bc4];
        store_A_frag(smu + AH_OFF, smu + AL_OFF, ar, ac4, pa);
        store_B_frag(smu + BH_OFF, smu + BL_OFF, bk, bc4, pb);
    }
    __syncthreads();

    const int a_coff = (warp_m * 4) * 128 + lane * 4;
    const int b_coff = warp_n * 288 + b_lane_off(lane);

    const int nt = K / 32;
    for (int ti = 0; ti < nt; ti++) {
        const int cur = ti & 1;
        const bool more = (ti + 1 < nt);
        float4 pa[4], pb[4];
        if (more) {
            const int k0n = (ti + 1) * 32;
#pragma unroll
            for (int i = 0; i < 4; i++)
                pa[i] = *(const float4*)&A[(size_t)(bm + ar + i * 32) * K + k0n + ac4];
#pragma unroll
            for (int i = 0; i < 4; i++)
                pb[i] = *(const float4*)&Bm[(size_t)(k0n + bk + i * 8) * N + bn + bc4];
        }

        const uint32_t* AHs = smu + cur * STAGE_U32 + AH_OFF;
        const uint32_t* ALs = smu + cur * STAGE_U32 + AL_OFF;
        const uint32_t* BHs = smu + cur * STAGE_U32 + BH_OFF;
        const uint32_t* BLs = smu + cur * STAGE_U32 + BL_OFF;

#pragma unroll
        for (int k8 = 0; k8 < 4; k8++) {
            uint32_t ah[4][4], al[4][4], bh[4][2], bl[4][2];
#pragma unroll
            for (int im = 0; im < 4; im++) {
                int off = k8 * 1024 + im * 128 + a_coff;
                *(uint4*)&ah[im][0] = *(const uint4*)&AHs[off];
                *(uint4*)&al[im][0] = *(const uint4*)&ALs[off];
            }
            {
                int off = k8 * 1152 + b_coff;
                *(uint4*)&bh[0][0] = *(const uint4*)&BHs[off];
                *(uint4*)&bh[2][0] = *(const uint4*)&BHs[off + 4];
                *(uint4*)&bl[0][0] = *(const uint4*)&BLs[off];
                *(uint4*)&bl[2][0] = *(const uint4*)&BLs[off + 4];
            }
#pragma unroll
            for (int im = 0; im < 4; im++)
#pragma unroll
                for (int jn = 0; jn < 4; jn++) {
                    mma8(acc[im][jn], al[im], bh[jn]);
                    mma8(acc[im][jn], ah[im], bl[jn]);
                    mma8(acc[im][jn], ah[im], bh[jn]);
                }
        }

        if (more) {
            uint32_t* nAH = smu + (cur ^ 1) * STAGE_U32 + AH_OFF;
            uint32_t* nAL = smu + (cur ^ 1) * STAGE_U32 + AL_OFF;
            uint32_t* nBH = smu + (cur ^ 1) * STAGE_U32 + BH_OFF;
            uint32_t* nBL = smu + (cur ^ 1) * STAGE_U32 + BL_OFF;
            store_A_frag(nAH, nAL, ar, ac4, pa);
            store_B_frag(nBH, nBL, bk, bc4, pb);
        }
        __syncthreads();
    }

    // epilogue: bias + optional GELU
#pragma unroll
    for (int im = 0; im < 4; im++) {
#pragma unroll
        for (int jn = 0; jn < 4; jn++) {
            int row = bm + warp_m * 64 + im * 16 + g;
            int col = bn + warp_n * 32 + jn * 8 + 2 * t;
            float bx = bias[col], by = bias[col + 1];
            float2 v0, v1;
            v0.x = acc[im][jn][0] + bx;
            v0.y = acc[im][jn][1] + by;
            v1.x = acc[im][jn][2] + bx;
            v1.y = acc[im][jn][3] + by;
            if (GELU) {
                v0.x = gelu_exact(v0.x); v0.y = gelu_exact(v0.y);
                v1.x = gelu_exact(v1.x); v1.y = gelu_exact(v1.y);
            }
            *(float2*)&C[(size_t)row * N + col] = v0;
            *(float2*)&C[(size_t)(row + 8) * N + col] = v1;
        }
    }
}

// ---------------- per-row sum of squares (one warp per row) ----------------
__global__ void rowsumsq_kernel(const float* __restrict__ src,
                                float* __restrict__ out, int rows)
{
    int warp = (blockIdx.x * blockDim.x + threadIdx.x) >> 5;
    int lane = threadIdx.x & 31;
    if (warp >= rows) return;
    const float* p = src + (size_t)warp * LAT;
    float s = 0.0f;
#pragma unroll
    for (int i = 0; i < LAT; i += 32) {
        float v = p[i + lane];
        s = fmaf(v, v, s);
    }
#pragma unroll
    for (int o = 16; o; o >>= 1) s += __shfl_down_sync(0xffffffffu, s, o);
    if (lane == 0) out[warp] = s;
}

// ---------------- distance + argmin: 64 rows x 4096 codes per block --------
__global__ void __launch_bounds__(256) dist_argmin_kernel(
    const float* __restrict__ embed)
{
    extern __shared__ float sm[];
    float* Zs = sm;
    float* Es = sm + 256 * 64;

    const int tid = threadIdx.x;
    const int row0 = blockIdx.x * 64;

    for (int tt = tid; tt < 64 * 64; tt += 256) {
        int r  = tt & 63;
        int kq = tt >> 6;
        float4 v = *(const float4*)(&g_ze[(size_t)(row0 + r) * LAT + kq * 4]);
        Zs[(kq * 4 + 0) * 64 + r] = v.x;
        Zs[(kq * 4 + 1) * 64 + r] = v.y;
        Zs[(kq * 4 + 2) * 64 + r] = v.z;
        Zs[(kq * 4 + 3) * 64 + r] = v.w;
    }

    const int ty = tid >> 4, tx = tid & 15;
    float bestv[4];
    int   besti[4];
#pragma unroll
    for (int i = 0; i < 4; i++) { bestv[i] = INFINITY; besti[i] = 0; }

    float zs[4];
#pragma unroll
    for (int i = 0; i < 4; i++) zs[i] = g_zsq[row0 + ty * 4 + i];

    for (int c0 = 0; c0 < KC; c0 += 64) {
        __syncthreads();
        for (int tt = tid; tt < 64 * 64; tt += 256) {
            int r  = tt & 63;
            int kq = tt >> 6;
            float4 v = *(const float4*)(&embed[(size_t)(c0 + r) * LAT + kq * 4]);
            Es[(kq * 4 + 0) * 64 + r] = v.x;
            Es[(kq * 4 + 1) * 64 + r] = v.y;
            Es[(kq * 4 + 2) * 64 + r] = v.z;
            Es[(kq * 4 + 3) * 64 + r] = v.w;
        }
        __syncthreads();

        ull acc2[4][2];
#pragma unroll
        for (int i = 0; i < 4; i++)
#pragma unroll
            for (int j = 0; j < 2; j++) acc2[i][j] = 0ull;

        for (int k = 0; k < 256; k++) {
            float rz[4];
            *(float4*)rz = *(const float4*)&Zs[k * 64 + ty * 4];
            ull re2[2];
            *(uint4*)&re2[0] = *(const uint4*)&Es[k * 64 + tx * 4];
#pragma unroll
            for (int i = 0; i < 4; i++) {
                ull z2 = pack2(rz[i], rz[i]);
#pragma unroll
                for (int j = 0; j < 2; j++)
                    fma2(acc2[i][j], z2, re2[j], acc2[i][j]);
            }
        }

#pragma unroll
        for (int i = 0; i < 4; i++) {
            float dot[4];
            unpack2(acc2[i][0], dot[0], dot[1]);
            unpack2(acc2[i][1], dot[2], dot[3]);
#pragma unroll
            for (int j = 0; j < 4; j++) {
                int c = c0 + tx * 4 + j;
                float t1 = zs[i] + g_esq[c];
                float v  = fmaf(-2.0f, dot[j], t1);
                if (v < bestv[i] || (v == bestv[i] && c < besti[i])) {
                    bestv[i] = v; besti[i] = c;
                }
            }
        }
    }

    __syncthreads();
    float* sval = Es;
    int*   sidx = (int*)(Es + 64 * 16);
#pragma unroll
    for (int i = 0; i < 4; i++) {
        sval[(ty * 4 + i) * 16 + tx] = bestv[i];
        sidx[(ty * 4 + i) * 16 + tx] = besti[i];
    }
    __syncthreads();
    if (tid < 64) {
        float bv = INFINITY; int bi = 0x7fffffff;
        for (int tt = 0; tt < 16; tt++) {
            float v = sval[tid * 16 + tt];
            int   c = sidx[tid * 16 + tt];
            if (v < bv || (v == bv && c < bi)) { bv = v; bi = c; }
        }
        g_idx[row0 + tid] = bi;
    }
}

// ---------------- gather z_q, per-row loss, indices out --------------------
__global__ void gather_loss_kernel(const float* __restrict__ embed,
                                   float* __restrict__ out_f, int write_extra)
{
    int warp = (blockIdx.x * blockDim.x + threadIdx.x) >> 5;
    int lane = threadIdx.x & 31;
    if (warp >= B_) return;
    int idx = g_idx[warp];
    const float* ze = g_ze + (size_t)warp * LAT;
    const float* eq = embed + (size_t)idx * LAT;
    float s = 0.0f;
#pragma unroll
    for (int i = 0; i < LAT; i += 32) {
        float q = eq[i + lane];
        float z = ze[i + lane];
        g_zq[(size_t)warp * LAT + i + lane] = q;
        float d = z - q;
        s = fmaf(d, d, s);
    }
#pragma unroll
    for (int o = 16; o; o >>= 1) s += __shfl_down_sync(0xffffffffu, s, o);
    if (lane == 0) {
        g_rowloss[warp] = s;
        if (write_extra)
            out_f[(size_t)B_ * DIN + 1 + warp] = (float)idx;
    }
}

// ---------------- final loss reduction (single block, fixed order) ---------
__global__ void loss_final_kernel(float* __restrict__ out_f, int write_extra)
{
    __shared__ float sh[256];
    float s = 0.0f;
    for (int i = threadIdx.x; i < B_; i += 256) s += g_rowloss[i];
    sh[threadIdx.x] = s;
    __syncthreads();
    for (int o = 128; o; o >>= 1) {
        if (threadIdx.x < o) sh[threadIdx.x] += sh[threadIdx.x + o];
        __syncthreads();
    }
    if (threadIdx.x == 0 && write_extra) {
        out_f[(size_t)B_ * DIN] = 1.25f * sh[0] / (float)((size_t)B_ * LAT);
    }
}

// ---------------- launch ----------------------------------------------------
extern "C" void kernel_launch(void* const* d_in, const int* in_sizes, int n_in,
                              void* d_out, int out_size)
{
    const float* x     = (const float*)d_in[0];
    const float* W1    = (const float*)d_in[1];
    const float* b1    = (const float*)d_in[2];
    const float* W2    = (const float*)d_in[3];
    const float* b2    = (const float*)d_in[4];
    const float* W3    = (const float*)d_in[5];
    const float* b3    = (const float*)d_in[6];
    const float* embed = (const float*)d_in[7];
    const float* D1    = (const float*)d_in[8];
    const float* d1    = (const float*)d_in[9];
    const float* D2    = (const float*)d_in[10];
    const float* d2    = (const float*)d_in[11];
    const float* D3    = (const float*)d_in[12];
    const float* d3    = (const float*)d_in[13];
    float* out = (float*)d_out;

    float *h1, *h2, *ze, *zq, *zsq, *esq;
    cudaGetSymbolAddress((void**)&h1,  g_h1);
    cudaGetSymbolAddress((void**)&h2,  g_h2);
    cudaGetSymbolAddress((void**)&ze,  g_ze);
    cudaGetSymbolAddress((void**)&zq,  g_zq);
    cudaGetSymbolAddress((void**)&zsq, g_zsq);
    cudaGetSymbolAddress((void**)&esq, g_esq);

    const int write_extra =
        ((size_t)out_size >= (size_t)B_ * DIN + 1 + B_) ? 1 : 0;

    cudaFuncSetAttribute(mma_gemm_bias_act<true>,
                         cudaFuncAttributeMaxDynamicSharedMemorySize, SM_BYTES);
    cudaFuncSetAttribute(mma_gemm_bias_act<false>,
                         cudaFuncAttributeMaxDynamicSharedMemorySize, SM_BYTES);

    // encoder — EXACT fp32 (FFMA2): indices bit-identical
    {
        dim3 g(HID / 128, B_ / 128);
        sgemm_bias_act<true><<<g, 256>>>(x, W1, b1, h1, B_, HID, DIN);
    }
    {
        dim3 g(HID / 128, B_ / 128);
        sgemm_bias_act<true><<<g, 256>>>(h1, W2, b2, h2, B_, HID, HID);
    }
    {
        dim3 g(LAT / 128, B_ / 128);
        sgemm_bias_act<false><<<g, 256>>>(h2, W3, b3, ze, B_, LAT, HID);
    }

    // norms
    rowsumsq_kernel<<<(B_ * 32) / 256, 256>>>(ze, zsq, B_);
    rowsumsq_kernel<<<(KC * 32) / 256, 256>>>(embed, esq, KC);

    // distance + argmin (exact)
    {
        int smem = 2 * 256 * 64 * (int)sizeof(float);  // 128 KB
        cudaFuncSetAttribute(dist_argmin_kernel,
                             cudaFuncAttributeMaxDynamicSharedMemorySize, smem);
        dist_argmin_kernel<<<B_ / 64, 256, smem>>>(embed);
    }

    // gather + loss
    gather_loss_kernel<<<(B_ * 32) / 256, 256>>>(embed, out, write_extra);
    loss_final_kernel<<<1, 256>>>(out, write_extra);

    // decoder — 3xTF32 tensor cores (bitwise-identical math to Round 4)
    {
        dim3 g(HID / 128, B_ / 128);
        mma_gemm_bias_act<true><<<g, 256, SM_BYTES>>>(zq, D1, d1, h1, B_, HID, LAT);
    }
    {
        dim3 g(HID / 128, B_ / 128);
        mma_gemm_bias_act<true><<<g, 256, SM_BYTES>>>(h1, D2, d2, h2, B_, HID, HID);
    }
    {
        dim3 g(DIN / 128, B_ / 128);
        mma_gemm_bias_act<false><<<g, 256, SM_BYTES>>>(h2, D3, d3, out, B_, DIN, HID);
    }
}

// round 6
// speedup vs baseline: 1.1477x; 1.1477x over previous
#include <cuda_runtime.h>
#include <cuda_bf16.h>
#include <math.h>
#include <stdint.h>

#define B_   8192
#define DIN  1024
#define HID  2048
#define LAT  256
#define KC   4096

typedef unsigned long long ull;

// ---------------- scratch (device globals; no allocation allowed) ----------
__device__ float g_h1[(size_t)B_ * HID];   // 64 MB
__device__ float g_h2[(size_t)B_ * HID];   // 64 MB
__device__ float g_ze[(size_t)B_ * LAT];   // 8 MB
__device__ float g_zq[(size_t)B_ * LAT];   // 8 MB
__device__ float g_zsq[B_];
__device__ float g_esq[KC];
__device__ float g_rowloss[B_];
__device__ int   g_idx[B_];

__device__ __forceinline__ float gelu_exact(float x) {
    return 0.5f * x * (1.0f + erff(x * 0.7071067811865476f));
}

// packed fp32x2 FMA: two independent rn-rounded fp32 FMAs (FFMA2)
__device__ __forceinline__ void fma2(ull& d, ull a, ull b, ull c) {
    asm("fma.rn.f32x2 %0, %1, %2, %3;" : "=l"(d) : "l"(a), "l"(b), "l"(c));
}
__device__ __forceinline__ ull pack2(float lo, float hi) {
    ull r;
    asm("mov.b64 %0, {%1, %2};" : "=l"(r) : "f"(lo), "f"(hi));
    return r;
}
__device__ __forceinline__ void unpack2(ull v, float& lo, float& hi) {
    asm("mov.b64 {%0, %1}, %2;" : "=f"(lo), "=f"(hi) : "l"(v));
}

// ================= EXACT encoder GEMM (FFMA2; bit-identical, R4 version) ===
template<bool GELU>
__global__ void __launch_bounds__(256, 2) sgemm_bias_act(
    const float* __restrict__ A, const float* __restrict__ Bm,
    const float* __restrict__ bias, float* __restrict__ C,
    int M, int N, int K)
{
    __shared__ float As[8][128];
    __shared__ float Bs[8][128];

    const int tid = threadIdx.x;
    const int bm = blockIdx.y * 128;
    const int bn = blockIdx.x * 128;

    const int arow = tid >> 1;
    const int acol = (tid & 1) * 4;
    const int brow = tid >> 5;
    const int bcol = (tid & 31) * 4;

    const int ty = tid >> 4;
    const int tx = tid & 15;

    ull acc2[8][4];
#pragma unroll
    for (int i = 0; i < 8; i++)
#pragma unroll
        for (int j = 0; j < 4; j++) acc2[i][j] = 0ull;

    const float* Aptr = A + (size_t)(bm + arow) * K + acol;
    const float* Bptr = Bm + (size_t)brow * N + bn + bcol;

    for (int k0 = 0; k0 < K; k0 += 8) {
        float4 a4 = *(const float4*)(Aptr + k0);
        As[acol + 0][arow] = a4.x;
        As[acol + 1][arow] = a4.y;
        As[acol + 2][arow] = a4.z;
        As[acol + 3][arow] = a4.w;
        float4 b4 = *(const float4*)(Bptr + (size_t)k0 * N);
        *(float4*)&Bs[brow][bcol] = b4;
        __syncthreads();

#pragma unroll
        for (int kk = 0; kk < 8; kk++) {
            float ra[8];
            *(float4*)(ra)     = *(const float4*)&As[kk][ty * 8];
            *(float4*)(ra + 4) = *(const float4*)&As[kk][ty * 8 + 4];
            ull rb2[4];
            *(uint4*)&rb2[0] = *(const uint4*)&Bs[kk][tx * 8];
            *(uint4*)&rb2[2] = *(const uint4*)&Bs[kk][tx * 8 + 4];
#pragma unroll
            for (int i = 0; i < 8; i++) {
                ull a2 = pack2(ra[i], ra[i]);
#pragma unroll
                for (int j = 0; j < 4; j++)
                    fma2(acc2[i][j], a2, rb2[j], acc2[i][j]);
            }
        }
        __syncthreads();
    }

#pragma unroll
    for (int i = 0; i < 8; i++) {
        int row = bm + ty * 8 + i;
#pragma unroll
        for (int j = 0; j < 4; j += 2) {
            int col = bn + tx * 8 + j * 2;
            float4 v;
            unpack2(acc2[i][j],     v.x, v.y);
            unpack2(acc2[i][j + 1], v.z, v.w);
            v.x += bias[col + 0];
            v.y += bias[col + 1];
            v.z += bias[col + 2];
            v.w += bias[col + 3];
            if (GELU) {
                v.x = gelu_exact(v.x); v.y = gelu_exact(v.y);
                v.z = gelu_exact(v.z); v.w = gelu_exact(v.w);
            }
            *(float4*)(C + (size_t)row * N + col) = v;
        }
    }
}

// ================= 3x-BF16 tensor-core GEMM (decoder only) =================
// m16n8k16 bf16 MMA; a = ah + al (bf16 split). D += al*bh + ah*bl + ah*bh.
// smem holds bf16x2 k-pairs (u32), row stride 20 u32 -> conflict-free
// fragment loads (rows g*20 hit banks {0,20,8,28,16,4,24,12} + t).
__device__ __forceinline__ uint32_t pack2bf(__nv_bfloat16 a, __nv_bfloat16 b) {
    __nv_bfloat162 v(a, b);
    return *reinterpret_cast<uint32_t*>(&v);
}
__device__ __forceinline__ void split_bf(float x, __nv_bfloat16& h, __nv_bfloat16& l) {
    h = __float2bfloat16_rn(x);
    l = __float2bfloat16_rn(x - __bfloat162float(h));
}

__device__ __forceinline__ void mma16(float* d, const uint32_t* a, const uint32_t* b) {
    asm("mma.sync.aligned.m16n8k16.row.col.f32.bf16.bf16.f32 "
        "{%0,%1,%2,%3}, {%4,%5,%6,%7}, {%8,%9}, {%0,%1,%2,%3};"
        : "+f"(d[0]), "+f"(d[1]), "+f"(d[2]), "+f"(d[3])
        : "r"(a[0]), "r"(a[1]), "r"(a[2]), "r"(a[3]), "r"(b[0]), "r"(b[1]));
}

#define LDA 20   // u32 stride (16 k-pairs + 4 pad)

template<bool GELU>
__global__ void __launch_bounds__(256) bf16_gemm_bias_act(
    const float* __restrict__ A, const float* __restrict__ Bm,
    const float* __restrict__ bias, float* __restrict__ C,
    int M, int N, int K)
{
    __shared__ uint32_t Ah[128 * LDA], Al[128 * LDA];
    __shared__ uint32_t Bh[128 * LDA], Bl[128 * LDA];

    const int tid  = threadIdx.x;
    const int wid  = tid >> 5;
    const int lane = tid & 31;
    const int g = lane >> 2;
    const int t = lane & 3;
    const int warp_m = wid & 1;
    const int warp_n = wid >> 1;
    const int bm = blockIdx.y * 128;
    const int bn = blockIdx.x * 128;

    float acc[4][4][4];
#pragma unroll
    for (int i = 0; i < 4; i++)
#pragma unroll
        for (int j = 0; j < 4; j++)
#pragma unroll
            for (int r = 0; r < 4; r++) acc[i][j][r] = 0.0f;

    // A fill: thread covers rows ar+32i, k = ac4..ac4+3
    const int ar  = tid >> 3;
    const int ac4 = (tid & 7) * 4;
    const int ac2 = (tid & 7) * 2;
    // B fill: thread covers col n_l, k-pairs k2b..k2b+7
    const int n_l = lane + 32 * (wid & 3);
    const int k2b = (wid >> 2) * 8;

    float4 pa[4];
    float  pb0[8], pb1[8];
#pragma unroll
    for (int i = 0; i < 4; i++)
        pa[i] = *(const float4*)&A[(size_t)(bm + ar + i * 32) * K + ac4];
#pragma unroll
    for (int q = 0; q < 8; q++) {
        int k = 2 * (k2b + q);
        pb0[q] = Bm[(size_t)k * N + bn + n_l];
        pb1[q] = Bm[(size_t)(k + 1) * N + bn + n_l];
    }

    for (int k0 = 0; k0 < K; k0 += 32) {
        // split + store current tile
#pragma unroll
        for (int i = 0; i < 4; i++) {
            int row = ar + i * 32;
            float v[4] = { pa[i].x, pa[i].y, pa[i].z, pa[i].w };
            __nv_bfloat16 h[4], l[4];
#pragma unroll
            for (int j = 0; j < 4; j++) split_bf(v[j], h[j], l[j]);
            Ah[row * LDA + ac2]     = pack2bf(h[0], h[1]);
            Ah[row * LDA + ac2 + 1] = pack2bf(h[2], h[3]);
            Al[row * LDA + ac2]     = pack2bf(l[0], l[1]);
            Al[row * LDA + ac2 + 1] = pack2bf(l[2], l[3]);
        }
#pragma unroll
        for (int q = 0; q < 8; q++) {
            __nv_bfloat16 h0, l0, h1, l1;
            split_bf(pb0[q], h0, l0);
            split_bf(pb1[q], h1, l1);
            Bh[n_l * LDA + k2b + q] = pack2bf(h0, h1);
            Bl[n_l * LDA + k2b + q] = pack2bf(l0, l1);
        }
        __syncthreads();

        // prefetch next tile
        if (k0 + 32 < K) {
#pragma unroll
            for (int i = 0; i < 4; i++)
                pa[i] = *(const float4*)&A[(size_t)(bm + ar + i * 32) * K + k0 + 32 + ac4];
#pragma unroll
            for (int q = 0; q < 8; q++) {
                int k = k0 + 32 + 2 * (k2b + q);
                pb0[q] = Bm[(size_t)k * N + bn + n_l];
                pb1[q] = Bm[(size_t)(k + 1) * N + bn + n_l];
            }
        }

        // two k16 steps
#pragma unroll
        for (int kk = 0; kk < 2; kk++) {
            const int ko = kk * 8;
            uint32_t ah[4][4], al[4][4], bh[4][2], bl[4][2];
#pragma unroll
            for (int im = 0; im < 4; im++) {
                int row = warp_m * 64 + im * 16 + g;
                int base = row * LDA + ko;
                ah[im][0] = Ah[base + t];
                ah[im][1] = Ah[base + 8 * LDA + t];
                ah[im][2] = Ah[base + t + 4];
                ah[im][3] = Ah[base + 8 * LDA + t + 4];
                al[im][0] = Al[base + t];
                al[im][1] = Al[base + 8 * LDA + t];
                al[im][2] = Al[base + t + 4];
                al[im][3] = Al[base + 8 * LDA + t + 4];
            }
#pragma unroll
            for (int jn = 0; jn < 4; jn++) {
                int n = warp_n * 32 + jn * 8 + g;
                int base = n * LDA + ko;
                bh[jn][0] = Bh[base + t];
                bh[jn][1] = Bh[base + t + 4];
                bl[jn][0] = Bl[base + t];
                bl[jn][1] = Bl[base + t + 4];
            }
#pragma unroll
            for (int im = 0; im < 4; im++)
#pragma unroll
                for (int jn = 0; jn < 4; jn++) {
                    mma16(acc[im][jn], al[im], bh[jn]);
                    mma16(acc[im][jn], ah[im], bl[jn]);
                    mma16(acc[im][jn], ah[im], bh[jn]);
                }
        }
        __syncthreads();
    }

    // epilogue: bias + optional GELU
#pragma unroll
    for (int im = 0; im < 4; im++) {
#pragma unroll
        for (int jn = 0; jn < 4; jn++) {
            int row = bm + warp_m * 64 + im * 16 + g;
            int col = bn + warp_n * 32 + jn * 8 + 2 * t;
            float bx = bias[col], by = bias[col + 1];
            float2 v0, v1;
            v0.x = acc[im][jn][0] + bx;
            v0.y = acc[im][jn][1] + by;
            v1.x = acc[im][jn][2] + bx;
            v1.y = acc[im][jn][3] + by;
            if (GELU) {
                v0.x = gelu_exact(v0.x); v0.y = gelu_exact(v0.y);
                v1.x = gelu_exact(v1.x); v1.y = gelu_exact(v1.y);
            }
            *(float2*)&C[(size_t)row * N + col] = v0;
            *(float2*)&C[(size_t)(row + 8) * N + col] = v1;
        }
    }
}

// ---------------- per-row sum of squares (one warp per row) ----------------
__global__ void rowsumsq_kernel(const float* __restrict__ src,
                                float* __restrict__ out, int rows)
{
    int warp = (blockIdx.x * blockDim.x + threadIdx.x) >> 5;
    int lane = threadIdx.x & 31;
    if (warp >= rows) return;
    const float* p = src + (size_t)warp * LAT;
    float s = 0.0f;
#pragma unroll
    for (int i = 0; i < LAT; i += 32) {
        float v = p[i + lane];
        s = fmaf(v, v, s);
    }
#pragma unroll
    for (int o = 16; o; o >>= 1) s += __shfl_down_sync(0xffffffffu, s, o);
    if (lane == 0) out[warp] = s;
}

// ---------------- distance + argmin: 64 rows x 4096 codes per block --------
__global__ void __launch_bounds__(256) dist_argmin_kernel(
    const float* __restrict__ embed)
{
    extern __shared__ float sm[];
    float* Zs = sm;
    float* Es = sm + 256 * 64;

    const int tid = threadIdx.x;
    const int row0 = blockIdx.x * 64;

    for (int tt = tid; tt < 64 * 64; tt += 256) {
        int r  = tt & 63;
        int kq = tt >> 6;
        float4 v = *(const float4*)(&g_ze[(size_t)(row0 + r) * LAT + kq * 4]);
        Zs[(kq * 4 + 0) * 64 + r] = v.x;
        Zs[(kq * 4 + 1) * 64 + r] = v.y;
        Zs[(kq * 4 + 2) * 64 + r] = v.z;
        Zs[(kq * 4 + 3) * 64 + r] = v.w;
    }

    const int ty = tid >> 4, tx = tid & 15;
    float bestv[4];
    int   besti[4];
#pragma unroll
    for (int i = 0; i < 4; i++) { bestv[i] = INFINITY; besti[i] = 0; }

    float zs[4];
#pragma unroll
    for (int i = 0; i < 4; i++) zs[i] = g_zsq[row0 + ty * 4 + i];

    for (int c0 = 0; c0 < KC; c0 += 64) {
        __syncthreads();
        for (int tt = tid; tt < 64 * 64; tt += 256) {
            int r  = tt & 63;
            int kq = tt >> 6;
            float4 v = *(const float4*)(&embed[(size_t)(c0 + r) * LAT + kq * 4]);
            Es[(kq * 4 + 0) * 64 + r] = v.x;
            Es[(kq * 4 + 1) * 64 + r] = v.y;
            Es[(kq * 4 + 2) * 64 + r] = v.z;
            Es[(kq * 4 + 3) * 64 + r] = v.w;
        }
        __syncthreads();

        ull acc2[4][2];
#pragma unroll
        for (int i = 0; i < 4; i++)
#pragma unroll
            for (int j = 0; j < 2; j++) acc2[i][j] = 0ull;

        for (int k = 0; k < 256; k++) {
            float rz[4];
            *(float4*)rz = *(const float4*)&Zs[k * 64 + ty * 4];
            ull re2[2];
            *(uint4*)&re2[0] = *(const uint4*)&Es[k * 64 + tx * 4];
#pragma unroll
            for (int i = 0; i < 4; i++) {
                ull z2 = pack2(rz[i], rz[i]);
#pragma unroll
                for (int j = 0; j < 2; j++)
                    fma2(acc2[i][j], z2, re2[j], acc2[i][j]);
            }
        }

#pragma unroll
        for (int i = 0; i < 4; i++) {
            float dot[4];
            unpack2(acc2[i][0], dot[0], dot[1]);
            unpack2(acc2[i][1], dot[2], dot[3]);
#pragma unroll
            for (int j = 0; j < 4; j++) {
                int c = c0 + tx * 4 + j;
                float t1 = zs[i] + g_esq[c];
                float v  = fmaf(-2.0f, dot[j], t1);
                if (v < bestv[i] || (v == bestv[i] && c < besti[i])) {
                    bestv[i] = v; besti[i] = c;
                }
            }
        }
    }

    __syncthreads();
    float* sval = Es;
    int*   sidx = (int*)(Es + 64 * 16);
#pragma unroll
    for (int i = 0; i < 4; i++) {
        sval[(ty * 4 + i) * 16 + tx] = bestv[i];
        sidx[(ty * 4 + i) * 16 + tx] = besti[i];
    }
    __syncthreads();
    if (tid < 64) {
        float bv = INFINITY; int bi = 0x7fffffff;
        for (int tt = 0; tt < 16; tt++) {
            float v = sval[tid * 16 + tt];
            int   c = sidx[tid * 16 + tt];
            if (v < bv || (v == bv && c < bi)) { bv = v; bi = c; }
        }
        g_idx[row0 + tid] = bi;
    }
}

// ---------------- gather z_q, per-row loss, indices out --------------------
__global__ void gather_loss_kernel(const float* __restrict__ embed,
                                   float* __restrict__ out_f, int write_extra)
{
    int warp = (blockIdx.x * blockDim.x + threadIdx.x) >> 5;
    int lane = threadIdx.x & 31;
    if (warp >= B_) return;
    int idx = g_idx[warp];
    const float* ze = g_ze + (size_t)warp * LAT;
    const float* eq = embed + (size_t)idx * LAT;
    float s = 0.0f;
#pragma unroll
    for (int i = 0; i < LAT; i += 32) {
        float q = eq[i + lane];
        float z = ze[i + lane];
        g_zq[(size_t)warp * LAT + i + lane] = q;
        float d = z - q;
        s = fmaf(d, d, s);
    }
#pragma unroll
    for (int o = 16; o; o >>= 1) s += __shfl_down_sync(0xffffffffu, s, o);
    if (lane == 0) {
        g_rowloss[warp] = s;
        if (write_extra)
            out_f[(size_t)B_ * DIN + 1 + warp] = (float)idx;
    }
}

// ---------------- final loss reduction (single block, fixed order) ---------
__global__ void loss_final_kernel(float* __restrict__ out_f, int write_extra)
{
    __shared__ float sh[256];
    float s = 0.0f;
    for (int i = threadIdx.x; i < B_; i += 256) s += g_rowloss[i];
    sh[threadIdx.x] = s;
    __syncthreads();
    for (int o = 128; o; o >>= 1) {
        if (threadIdx.x < o) sh[threadIdx.x] += sh[threadIdx.x + o];
        __syncthreads();
    }
    if (threadIdx.x == 0 && write_extra) {
        out_f[(size_t)B_ * DIN] = 1.25f * sh[0] / (float)((size_t)B_ * LAT);
    }
}

// ---------------- launch ----------------------------------------------------
extern "C" void kernel_launch(void* const* d_in, const int* in_sizes, int n_in,
                              void* d_out, int out_size)
{
    const float* x     = (const float*)d_in[0];
    const float* W1    = (const float*)d_in[1];
    const float* b1    = (const float*)d_in[2];
    const float* W2    = (const float*)d_in[3];
    const float* b2    = (const float*)d_in[4];
    const float* W3    = (const float*)d_in[5];
    const float* b3    = (const float*)d_in[6];
    const float* embed = (const float*)d_in[7];
    const float* D1    = (const float*)d_in[8];
    const float* d1    = (const float*)d_in[9];
    const float* D2    = (const float*)d_in[10];
    const float* d2    = (const float*)d_in[11];
    const float* D3    = (const float*)d_in[12];
    const float* d3    = (const float*)d_in[13];
    float* out = (float*)d_out;

    float *h1, *h2, *ze, *zq, *zsq, *esq;
    cudaGetSymbolAddress((void**)&h1,  g_h1);
    cudaGetSymbolAddress((void**)&h2,  g_h2);
    cudaGetSymbolAddress((void**)&ze,  g_ze);
    cudaGetSymbolAddress((void**)&zq,  g_zq);
    cudaGetSymbolAddress((void**)&zsq, g_zsq);
    cudaGetSymbolAddress((void**)&esq, g_esq);

    const int write_extra =
        ((size_t)out_size >= (size_t)B_ * DIN + 1 + B_) ? 1 : 0;

    // encoder — EXACT fp32 (FFMA2): indices bit-identical
    {
        dim3 g(HID / 128, B_ / 128);
        sgemm_bias_act<true><<<g, 256>>>(x, W1, b1, h1, B_, HID, DIN);
    }
    {
        dim3 g(HID / 128, B_ / 128);
        sgemm_bias_act<true><<<g, 256>>>(h1, W2, b2, h2, B_, HID, HID);
    }
    {
        dim3 g(LAT / 128, B_ / 128);
        sgemm_bias_act<false><<<g, 256>>>(h2, W3, b3, ze, B_, LAT, HID);
    }

    // norms
    rowsumsq_kernel<<<(B_ * 32) / 256, 256>>>(ze, zsq, B_);
    rowsumsq_kernel<<<(KC * 32) / 256, 256>>>(embed, esq, KC);

    // distance + argmin (exact)
    {
        int smem = 2 * 256 * 64 * (int)sizeof(float);  // 128 KB
        cudaFuncSetAttribute(dist_argmin_kernel,
                             cudaFuncAttributeMaxDynamicSharedMemorySize, smem);
        dist_argmin_kernel<<<B_ / 64, 256, smem>>>(embed);
    }

    // gather + loss
    gather_loss_kernel<<<(B_ * 32) / 256, 256>>>(embed, out, write_extra);
    loss_final_kernel<<<1, 256>>>(out, write_extra);

    // decoder — 3x-BF16 tensor cores (half the MMA count of 3xTF32)
    {
        dim3 g(HID / 128, B_ / 128);
        bf16_gemm_bias_act<true><<<g, 256>>>(zq, D1, d1, h1, B_, HID, LAT);
    }
    {
        dim3 g(HID / 128, B_ / 128);
        bf16_gemm_bias_act<true><<<g, 256>>>(h1, D2, d2, h2, B_, HID, HID);
    }
    {
        dim3 g(DIN / 128, B_ / 128);
        bf16_gemm_bias_act<false><<<g, 256>>>(h2, D3, d3, out, B_, DIN, HID);
    }
}

// round 7
// speedup vs baseline: 1.1495x; 1.0016x over previous
#include <cuda_runtime.h>
#include <cuda_bf16.h>
#include <math.h>
#include <stdint.h>

#define B_   8192
#define DIN  1024
#define HID  2048
#define LAT  256
#define KC   4096

typedef unsigned long long ull;

// ---------------- scratch (device globals; no allocation allowed) ----------
__device__ __align__(128) float g_h1[(size_t)B_ * HID];   // 64 MB (enc h1; reused: dec h1 split)
__device__ __align__(128) float g_h2[(size_t)B_ * HID];   // 64 MB (enc h2; reused: dec h2 split)
__device__ __align__(128) float g_ze[(size_t)B_ * LAT];   // 8 MB
__device__ float g_zsq[B_];
__device__ float g_esq[KC];
__device__ float g_rowloss[B_];
__device__ int   g_idx[B_];
// presplit buffers (bf16x2 k-pairs, [N or M rows][K/2] u32)
__device__ __align__(128) uint32_t g_zqh[(size_t)B_ * (LAT/2)];     // 4 MB
__device__ __align__(128) uint32_t g_zql[(size_t)B_ * (LAT/2)];
__device__ __align__(128) uint32_t g_d1h[(size_t)HID * (LAT/2)];    // 1 MB
__device__ __align__(128) uint32_t g_d1l[(size_t)HID * (LAT/2)];
__device__ __align__(128) uint32_t g_d2h[(size_t)HID * (HID/2)];    // 8 MB
__device__ __align__(128) uint32_t g_d2l[(size_t)HID * (HID/2)];
__device__ __align__(128) uint32_t g_d3h[(size_t)DIN * (HID/2)];    // 4 MB
__device__ __align__(128) uint32_t g_d3l[(size_t)DIN * (HID/2)];

__device__ __forceinline__ float gelu_exact(float x) {
    return 0.5f * x * (1.0f + erff(x * 0.7071067811865476f));
}

// packed fp32x2 FMA
__device__ __forceinline__ void fma2(ull& d, ull a, ull b, ull c) {
    asm("fma.rn.f32x2 %0, %1, %2, %3;" : "=l"(d) : "l"(a), "l"(b), "l"(c));
}
__device__ __forceinline__ ull pack2(float lo, float hi) {
    ull r;
    asm("mov.b64 %0, {%1, %2};" : "=l"(r) : "f"(lo), "f"(hi));
    return r;
}
__device__ __forceinline__ void unpack2(ull v, float& lo, float& hi) {
    asm("mov.b64 {%0, %1}, %2;" : "=f"(lo), "=f"(hi) : "l"(v));
}

// bf16 split helpers (same formulas as Round 6 -> identical values)
__device__ __forceinline__ uint32_t pack2bf(__nv_bfloat16 a, __nv_bfloat16 b) {
    __nv_bfloat162 v(a, b);
    return *reinterpret_cast<uint32_t*>(&v);
}
__device__ __forceinline__ void split_bf(float x, __nv_bfloat16& h, __nv_bfloat16& l) {
    h = __float2bfloat16_rn(x);
    l = __float2bfloat16_rn(x - __bfloat162float(h));
}
__device__ __forceinline__ uint32_t split_pair_hi(float x0, float x1) {
    __nv_bfloat16 h0, l0, h1, l1;
    split_bf(x0, h0, l0); split_bf(x1, h1, l1);
    return pack2bf(h0, h1);
}
__device__ __forceinline__ uint32_t split_pair_lo(float x0, float x1) {
    __nv_bfloat16 h0, l0, h1, l1;
    split_bf(x0, h0, l0); split_bf(x1, h1, l1);
    return pack2bf(l0, l1);
}

// ================= EXACT encoder GEMM (FFMA2; bit-identical) ===============
template<bool GELU>
__global__ void __launch_bounds__(256, 2) sgemm_bias_act(
    const float* __restrict__ A, const float* __restrict__ Bm,
    const float* __restrict__ bias, float* __restrict__ C,
    int M, int N, int K)
{
    __shared__ float As[8][128];
    __shared__ float Bs[8][128];

    const int tid = threadIdx.x;
    const int bm = blockIdx.y * 128;
    const int bn = blockIdx.x * 128;

    const int arow = tid >> 1;
    const int acol = (tid & 1) * 4;
    const int brow = tid >> 5;
    const int bcol = (tid & 31) * 4;

    const int ty = tid >> 4;
    const int tx = tid & 15;

    ull acc2[8][4];
#pragma unroll
    for (int i = 0; i < 8; i++)
#pragma unroll
        for (int j = 0; j < 4; j++) acc2[i][j] = 0ull;

    const float* Aptr = A + (size_t)(bm + arow) * K + acol;
    const float* Bptr = Bm + (size_t)brow * N + bn + bcol;

    for (int k0 = 0; k0 < K; k0 += 8) {
        float4 a4 = *(const float4*)(Aptr + k0);
        As[acol + 0][arow] = a4.x;
        As[acol + 1][arow] = a4.y;
        As[acol + 2][arow] = a4.z;
        As[acol + 3][arow] = a4.w;
        float4 b4 = *(const float4*)(Bptr + (size_t)k0 * N);
        *(float4*)&Bs[brow][bcol] = b4;
        __syncthreads();

#pragma unroll
        for (int kk = 0; kk < 8; kk++) {
            float ra[8];
            *(float4*)(ra)     = *(const float4*)&As[kk][ty * 8];
            *(float4*)(ra + 4) = *(const float4*)&As[kk][ty * 8 + 4];
            ull rb2[4];
            *(uint4*)&rb2[0] = *(const uint4*)&Bs[kk][tx * 8];
            *(uint4*)&rb2[2] = *(const uint4*)&Bs[kk][tx * 8 + 4];
#pragma unroll
            for (int i = 0; i < 8; i++) {
                ull a2 = pack2(ra[i], ra[i]);
#pragma unroll
                for (int j = 0; j < 4; j++)
                    fma2(acc2[i][j], a2, rb2[j], acc2[i][j]);
            }
        }
        __syncthreads();
    }

#pragma unroll
    for (int i = 0; i < 8; i++) {
        int row = bm + ty * 8 + i;
#pragma unroll
        for (int j = 0; j < 4; j += 2) {
            int col = bn + tx * 8 + j * 2;
            float4 v;
            unpack2(acc2[i][j],     v.x, v.y);
            unpack2(acc2[i][j + 1], v.z, v.w);
            v.x += bias[col + 0];
            v.y += bias[col + 1];
            v.z += bias[col + 2];
            v.w += bias[col + 3];
            if (GELU) {
                v.x = gelu_exact(v.x); v.y = gelu_exact(v.y);
                v.z = gelu_exact(v.z); v.w = gelu_exact(v.w);
            }
            *(float4*)(C + (size_t)row * N + col) = v;
        }
    }
}

// ================= weight transpose-split prep ==============================
// B[K,N] fp32 -> Oh/Ol[N][K/2] u32 (bf16x2 k-pairs). grid (N/32, K/64), 256 thr.
__global__ void wsplit_kernel(const float* __restrict__ B, int K, int N,
                              uint32_t* __restrict__ Oh, uint32_t* __restrict__ Ol)
{
    __shared__ float t[64][33];
    const int n0 = blockIdx.x * 32;
    const int k0 = blockIdx.y * 64;
    const int tid = threadIdx.x;
#pragma unroll
    for (int i = 0; i < 8; i++) {
        int idx = tid + i * 256;
        int kk = idx >> 5, nn = idx & 31;
        t[kk][nn] = B[(size_t)(k0 + kk) * N + n0 + nn];
    }
    __syncthreads();
    const int Kp = K >> 1;
#pragma unroll
    for (int i = 0; i < 4; i++) {
        int idx = tid + i * 256;
        int nn = idx >> 5, kp = idx & 31;
        float x0 = t[2 * kp][nn], x1 = t[2 * kp + 1][nn];
        size_t o = (size_t)(n0 + nn) * Kp + (k0 >> 1) + kp;
        Oh[o] = split_pair_hi(x0, x1);
        Ol[o] = split_pair_lo(x0, x1);
    }
}

// ================= presplit 3x-BF16 tensor-core GEMM (decoder) =============
// A: [M][K/2] u32 hi/lo, B: [N][K/2] u32 hi/lo. MMA sequence identical to R6.
// MODE 0: fp32 out (no gelu). MODE 1: gelu, split output -> Oh/Ol [M][N/2].
__device__ __forceinline__ void mma16(float* d, const uint32_t* a, const uint32_t* b) {
    asm("mma.sync.aligned.m16n8k16.row.col.f32.bf16.bf16.f32 "
        "{%0,%1,%2,%3}, {%4,%5,%6,%7}, {%8,%9}, {%0,%1,%2,%3};"
        : "+f"(d[0]), "+f"(d[1]), "+f"(d[2]), "+f"(d[3])
        : "r"(a[0]), "r"(a[1]), "r"(a[2]), "r"(a[3]), "r"(b[0]), "r"(b[1]));
}

#define LDA 20   // u32 row stride (16 kp + 4 pad)

template<int MODE>
__global__ void __launch_bounds__(256) bf16ps_gemm(
    const uint32_t* __restrict__ Ah_g, const uint32_t* __restrict__ Al_g,
    const uint32_t* __restrict__ Bh_g, const uint32_t* __restrict__ Bl_g,
    const float* __restrict__ bias, float* __restrict__ C,
    uint32_t* __restrict__ Oh, uint32_t* __restrict__ Ol,
    int M, int N, int K)
{
    __shared__ uint32_t Ah[128 * LDA], Al[128 * LDA];
    __shared__ uint32_t Bh[128 * LDA], Bl[128 * LDA];

    const int tid  = threadIdx.x;
    const int wid  = tid >> 5;
    const int lane = tid & 31;
    const int g = lane >> 2;
    const int t = lane & 3;
    const int warp_m = wid & 1;
    const int warp_n = wid >> 1;
    const int bm = blockIdx.y * 128;
    const int bn = blockIdx.x * 128;
    const int Kp = K >> 1;

    float acc[4][4][4];
#pragma unroll
    for (int i = 0; i < 4; i++)
#pragma unroll
        for (int j = 0; j < 4; j++)
#pragma unroll
            for (int r = 0; r < 4; r++) acc[i][j][r] = 0.0f;

    const int fr = tid >> 1;            // 0..127
    const int fo = (tid & 1) * 8;       // 0 or 8
    const uint32_t* pAh = Ah_g + (size_t)(bm + fr) * Kp + fo;
    const uint32_t* pAl = Al_g + (size_t)(bm + fr) * Kp + fo;
    const uint32_t* pBh = Bh_g + (size_t)(bn + fr) * Kp + fo;
    const uint32_t* pBl = Bl_g + (size_t)(bn + fr) * Kp + fo;

    uint4 vah[2], val_[2], vbh[2], vbl[2];
#pragma unroll
    for (int q = 0; q < 2; q++) {
        vah[q]  = *(const uint4*)(pAh + q * 4);
        val_[q] = *(const uint4*)(pAl + q * 4);
        vbh[q]  = *(const uint4*)(pBh + q * 4);
        vbl[q]  = *(const uint4*)(pBl + q * 4);
    }

    const int nt = K / 32;
    for (int kt = 0; kt < nt; kt++) {
        // store staged tile
#pragma unroll
        for (int q = 0; q < 2; q++) {
            *(uint4*)&Ah[fr * LDA + fo + q * 4] = vah[q];
            *(uint4*)&Al[fr * LDA + fo + q * 4] = val_[q];
            *(uint4*)&Bh[fr * LDA + fo + q * 4] = vbh[q];
            *(uint4*)&Bl[fr * LDA + fo + q * 4] = vbl[q];
        }
        __syncthreads();

        if (kt + 1 < nt) {
            const int off = (kt + 1) * 16;
#pragma unroll
            for (int q = 0; q < 2; q++) {
                vah[q]  = *(const uint4*)(pAh + off + q * 4);
                val_[q] = *(const uint4*)(pAl + off + q * 4);
                vbh[q]  = *(const uint4*)(pBh + off + q * 4);
                vbl[q]  = *(const uint4*)(pBl + off + q * 4);
            }
        }

#pragma unroll
        for (int kk = 0; kk < 2; kk++) {
            const int ko = kk * 8;
            uint32_t ah[4][4], al[4][4], bh[4][2], bl[4][2];
#pragma unroll
            for (int im = 0; im < 4; im++) {
                int row = warp_m * 64 + im * 16 + g;
                int base = row * LDA + ko;
                ah[im][0] = Ah[base + t];
                ah[im][1] = Ah[base + 8 * LDA + t];
                ah[im][2] = Ah[base + t + 4];
                ah[im][3] = Ah[base + 8 * LDA + t + 4];
                al[im][0] = Al[base + t];
                al[im][1] = Al[base + 8 * LDA + t];
                al[im][2] = Al[base + t + 4];
                al[im][3] = Al[base + 8 * LDA + t + 4];
            }
#pragma unroll
            for (int jn = 0; jn < 4; jn++) {
                int n = warp_n * 32 + jn * 8 + g;
                int base = n * LDA + ko;
                bh[jn][0] = Bh[base + t];
                bh[jn][1] = Bh[base + t + 4];
                bl[jn][0] = Bl[base + t];
                bl[jn][1] = Bl[base + t + 4];
            }
#pragma unroll
            for (int im = 0; im < 4; im++)
#pragma unroll
                for (int jn = 0; jn < 4; jn++) {
                    mma16(acc[im][jn], al[im], bh[jn]);
                    mma16(acc[im][jn], ah[im], bl[jn]);
                    mma16(acc[im][jn], ah[im], bh[jn]);
                }
        }
        __syncthreads();
    }

    // epilogue
#pragma unroll
    for (int im = 0; im < 4; im++) {
#pragma unroll
        for (int jn = 0; jn < 4; jn++) {
            int row = bm + warp_m * 64 + im * 16 + g;
            int col = bn + warp_n * 32 + jn * 8 + 2 * t;
            float bx = bias[col], by = bias[col + 1];
            float2 v0, v1;
            v0.x = acc[im][jn][0] + bx;
            v0.y = acc[im][jn][1] + by;
            v1.x = acc[im][jn][2] + bx;
            v1.y = acc[im][jn][3] + by;
            if (MODE == 1) {
                v0.x = gelu_exact(v0.x); v0.y = gelu_exact(v0.y);
                v1.x = gelu_exact(v1.x); v1.y = gelu_exact(v1.y);
                size_t o0 = (size_t)row * (N >> 1) + (col >> 1);
                size_t o1 = (size_t)(row + 8) * (N >> 1) + (col >> 1);
                Oh[o0] = split_pair_hi(v0.x, v0.y);
                Ol[o0] = split_pair_lo(v0.x, v0.y);
                Oh[o1] = split_pair_hi(v1.x, v1.y);
                Ol[o1] = split_pair_lo(v1.x, v1.y);
            } else {
                *(float2*)&C[(size_t)row * N + col] = v0;
                *(float2*)&C[(size_t)(row + 8) * N + col] = v1;
            }
        }
    }
}

// ---------------- per-row sum of squares (one warp per row) ----------------
__global__ void rowsumsq_kernel(const float* __restrict__ src,
                                float* __restrict__ out, int rows)
{
    int warp = (blockIdx.x * blockDim.x + threadIdx.x) >> 5;
    int lane = threadIdx.x & 31;
    if (warp >= rows) return;
    const float* p = src + (size_t)warp * LAT;
    float s = 0.0f;
#pragma unroll
    for (int i = 0; i < LAT; i += 32) {
        float v = p[i + lane];
        s = fmaf(v, v, s);
    }
#pragma unroll
    for (int o = 16; o; o >>= 1) s += __shfl_down_sync(0xffffffffu, s, o);
    if (lane == 0) out[warp] = s;
}

// ---------------- distance + argmin: 64 rows x 4096 codes per block --------
// 8x8 per thread; per-code dot is the same k-ascending fp32 chain as before
// (bit-identical dists/indices). Dynamic smem: Es[64][256] + Zs[64][64].
__global__ void __launch_bounds__(256) dist_argmin_kernel(
    const float* __restrict__ embed)
{
    extern __shared__ float sm[];
    float* Es = sm;                  // [64 k][256 codes]
    float* Zs = sm + 64 * 256;       // [64 k][64 rows]

    const int tid = threadIdx.x;
    const int tx = tid & 31;         // code group (8 codes)
    const int ty = tid >> 5;         // row group (8 rows)
    const int row0 = blockIdx.x * 64;

    float bestv[8];
    int   besti[8];
#pragma unroll
    for (int i = 0; i < 8; i++) { bestv[i] = INFINITY; besti[i] = 0; }

    float zs[8];
#pragma unroll
    for (int i = 0; i < 8; i++) zs[i] = g_zsq[row0 + ty * 8 + i];

    const int zr = tid & 63;         // Zs fill: row
    const int zq = tid >> 6;         // Zs fill: k quarter (0..3)

    for (int c0 = 0; c0 < KC; c0 += 256) {
        ull acc2[8][4];
#pragma unroll
        for (int i = 0; i < 8; i++)
#pragma unroll
            for (int j = 0; j < 4; j++) acc2[i][j] = 0ull;

        for (int ks = 0; ks < 256; ks += 64) {
            __syncthreads();
            // Es fill: thread -> one code, 64 k values
            {
                const float4* ep = (const float4*)(embed + (size_t)(c0 + tid) * LAT + ks);
#pragma unroll
                for (int q = 0; q < 16; q++) {
                    float4 v = ep[q];
                    Es[(4 * q + 0) * 256 + tid] = v.x;
                    Es[(4 * q + 1) * 256 + tid] = v.y;
                    Es[(4 * q + 2) * 256 + tid] = v.z;
                    Es[(4 * q + 3) * 256 + tid] = v.w;
                }
            }
            // Zs fill
            {
                const float4* zp = (const float4*)(g_ze + (size_t)(row0 + zr) * LAT + ks + zq * 16);
#pragma unroll
                for (int q = 0; q < 4; q++) {
                    float4 v = zp[q];
                    int kb = zq * 16 + 4 * q;
                    Zs[(kb + 0) * 64 + zr] = v.x;
                    Zs[(kb + 1) * 64 + zr] = v.y;
                    Zs[(kb + 2) * 64 + zr] = v.z;
                    Zs[(kb + 3) * 64 + zr] = v.w;
                }
            }
            __syncthreads();

            for (int k = 0; k < 64; k++) {
                float rz[8];
                *(float4*)(rz)     = *(const float4*)&Zs[k * 64 + ty * 8];
                *(float4*)(rz + 4) = *(const float4*)&Zs[k * 64 + ty * 8 + 4];
                ull re2[4];
                *(uint4*)&re2[0] = *(const uint4*)&Es[k * 256 + tx * 8];
                *(uint4*)&re2[2] = *(const uint4*)&Es[k * 256 + tx * 8 + 4];
#pragma unroll
                for (int i = 0; i < 8; i++) {
                    ull z2 = pack2(rz[i], rz[i]);
#pragma unroll
                    for (int j = 0; j < 4; j++)
                        fma2(acc2[i][j], z2, re2[j], acc2[i][j]);
                }
            }
        }

        // dist + best update for this 256-code chunk
#pragma unroll
        for (int i = 0; i < 8; i++) {
            float dot[8];
            unpack2(acc2[i][0], dot[0], dot[1]);
            unpack2(acc2[i][1], dot[2], dot[3]);
            unpack2(acc2[i][2], dot[4], dot[5]);
            unpack2(acc2[i][3], dot[6], dot[7]);
#pragma unroll
            for (int j = 0; j < 8; j++) {
                int c = c0 + tx * 8 + j;
                float t1 = zs[i] + g_esq[c];
                float v  = fmaf(-2.0f, dot[j], t1);
                if (v < bestv[i] || (v == bestv[i] && c < besti[i])) {
                    bestv[i] = v; besti[i] = c;
                }
            }
        }
    }

    // final reduce: 32 candidates per row
    __syncthreads();
    float* sval = sm;                       // [64][32]
    int*   sidx = (int*)(sm + 64 * 32);
#pragma unroll
    for (int i = 0; i < 8; i++) {
        sval[(ty * 8 + i) * 32 + tx] = bestv[i];
        sidx[(ty * 8 + i) * 32 + tx] = besti[i];
    }
    __syncthreads();
    if (tid < 64) {
        float bv = INFINITY; int bi = 0x7fffffff;
        for (int tt = 0; tt < 32; tt++) {
            float v = sval[tid * 32 + tt];
            int   c = sidx[tid * 32 + tt];
            if (v < bv || (v == bv && c < bi)) { bv = v; bi = c; }
        }
        g_idx[row0 + tid] = bi;
    }
}

// ---------------- gather z_q (split), per-row loss, indices out ------------
__global__ void gather_loss_kernel(const float* __restrict__ embed,
                                   float* __restrict__ out_f, int write_extra)
{
    int warp = (blockIdx.x * blockDim.x + threadIdx.x) >> 5;
    int lane = threadIdx.x & 31;
    if (warp >= B_) return;
    int idx = g_idx[warp];
    const float* ze = g_ze + (size_t)warp * LAT;
    const float* eq = embed + (size_t)idx * LAT;
    // loss loop: EXACT same order as Round 6 (bitwise-identical rowloss)
    float s = 0.0f;
#pragma unroll
    for (int i = 0; i < LAT; i += 32) {
        float q = eq[i + lane];
        float z = ze[i + lane];
        float d = z - q;
        s = fmaf(d, d, s);
    }
#pragma unroll
    for (int o = 16; o; o >>= 1) s += __shfl_down_sync(0xffffffffu, s, o);
    // split writes (same split values the decoder used to compute in-loop)
#pragma unroll
    for (int m = 0; m < LAT / 2; m += 32) {
        int kp = m + lane;
        float q0 = eq[2 * kp], q1 = eq[2 * kp + 1];
        g_zqh[(size_t)warp * (LAT / 2) + kp] = split_pair_hi(q0, q1);
        g_zql[(size_t)warp * (LAT / 2) + kp] = split_pair_lo(q0, q1);
    }
    if (lane == 0) {
        g_rowloss[warp] = s;
        if (write_extra)
            out_f[(size_t)B_ * DIN + 1 + warp] = (float)idx;
    }
}

// ---------------- final loss reduction (single block, fixed order) ---------
__global__ void loss_final_kernel(float* __restrict__ out_f, int write_extra)
{
    __shared__ float sh[256];
    float s = 0.0f;
    for (int i = threadIdx.x; i < B_; i += 256) s += g_rowloss[i];
    sh[threadIdx.x] = s;
    __syncthreads();
    for (int o = 128; o; o >>= 1) {
        if (threadIdx.x < o) sh[threadIdx.x] += sh[threadIdx.x + o];
        __syncthreads();
    }
    if (threadIdx.x == 0 && write_extra) {
        out_f[(size_t)B_ * DIN] = 1.25f * sh[0] / (float)((size_t)B_ * LAT);
    }
}

// ---------------- launch ----------------------------------------------------
extern "C" void kernel_launch(void* const* d_in, const int* in_sizes, int n_in,
                              void* d_out, int out_size)
{
    const float* x     = (const float*)d_in[0];
    const float* W1    = (const float*)d_in[1];
    const float* b1    = (const float*)d_in[2];
    const float* W2    = (const float*)d_in[3];
    const float* b2    = (const float*)d_in[4];
    const float* W3    = (const float*)d_in[5];
    const float* b3    = (const float*)d_in[6];
    const float* embed = (const float*)d_in[7];
    const float* D1    = (const float*)d_in[8];
    const float* d1    = (const float*)d_in[9];
    const float* D2    = (const float*)d_in[10];
    const float* d2    = (const float*)d_in[11];
    const float* D3    = (const float*)d_in[12];
    const float* d3    = (const float*)d_in[13];
    float* out = (float*)d_out;

    float *h1, *h2, *ze;
    uint32_t *zqh, *zql, *d1h, *d1l, *d2h, *d2l, *d3h, *d3l;
    float *zsq, *esq;
    cudaGetSymbolAddress((void**)&h1,  g_h1);
    cudaGetSymbolAddress((void**)&h2,  g_h2);
    cudaGetSymbolAddress((void**)&ze,  g_ze);
    cudaGetSymbolAddress((void**)&zsq, g_zsq);
    cudaGetSymbolAddress((void**)&esq, g_esq);
    cudaGetSymbolAddress((void**)&zqh, g_zqh);
    cudaGetSymbolAddress((void**)&zql, g_zql);
    cudaGetSymbolAddress((void**)&d1h, g_d1h);
    cudaGetSymbolAddress((void**)&d1l, g_d1l);
    cudaGetSymbolAddress((void**)&d2h, g_d2h);
    cudaGetSymbolAddress((void**)&d2l, g_d2l);
    cudaGetSymbolAddress((void**)&d3h, g_d3h);
    cudaGetSymbolAddress((void**)&d3l, g_d3l);

    // decoder h-splits reuse encoder fp32 scratch (encoder is done by then)
    uint32_t* h1h = (uint32_t*)h1;
    uint32_t* h1l = h1h + (size_t)B_ * (HID / 2);
    uint32_t* h2h = (uint32_t*)h2;
    uint32_t* h2l = h2h + (size_t)B_ * (HID / 2);

    const int write_extra =
        ((size_t)out_size >= (size_t)B_ * DIN + 1 + B_) ? 1 : 0;

    // weight presplit (independent of encoder)
    wsplit_kernel<<<dim3(HID / 32, LAT / 64), 256>>>(D1, LAT, HID, d1h, d1l);
    wsplit_kernel<<<dim3(HID / 32, HID / 64), 256>>>(D2, HID, HID, d2h, d2l);
    wsplit_kernel<<<dim3(DIN / 32, HID / 64), 256>>>(D3, HID, DIN, d3h, d3l);

    // encoder — EXACT fp32 (FFMA2): indices bit-identical
    {
        dim3 g(HID / 128, B_ / 128);
        sgemm_bias_act<true><<<g, 256>>>(x, W1, b1, h1, B_, HID, DIN);
    }
    {
        dim3 g(HID / 128, B_ / 128);
        sgemm_bias_act<true><<<g, 256>>>(h1, W2, b2, h2, B_, HID, HID);
    }
    {
        dim3 g(LAT / 128, B_ / 128);
        sgemm_bias_act<false><<<g, 256>>>(h2, W3, b3, ze, B_, LAT, HID);
    }

    // norms
    rowsumsq_kernel<<<(B_ * 32) / 256, 256>>>(ze, zsq, B_);
    rowsumsq_kernel<<<(KC * 32) / 256, 256>>>(embed, esq, KC);

    // distance + argmin (bit-identical dots)
    {
        int smem = (64 * 256 + 64 * 64) * (int)sizeof(float);  // 80 KB
        cudaFuncSetAttribute(dist_argmin_kernel,
                             cudaFuncAttributeMaxDynamicSharedMemorySize, smem);
        dist_argmin_kernel<<<B_ / 64, 256, smem>>>(embed);
    }

    // gather (+ zq split) + loss
    gather_loss_kernel<<<(B_ * 32) / 256, 256>>>(embed, out, write_extra);
    loss_final_kernel<<<1, 256>>>(out, write_extra);

    // decoder — presplit 3x-BF16 tensor cores (bitwise-identical to R6)
    {
        dim3 g(HID / 128, B_ / 128);
        bf16ps_gemm<1><<<g, 256>>>(zqh, zql, d1h, d1l, d1, nullptr,
                                   h1h, h1l, B_, HID, LAT);
    }
    {
        dim3 g(HID / 128, B_ / 128);
        bf16ps_gemm<1><<<g, 256>>>(h1h, h1l, d2h, d2l, d2, nullptr,
                                   h2h, h2l, B_, HID, HID);
    }
    {
        dim3 g(DIN / 128, B_ / 128);
        bf16ps_gemm<0><<<g, 256>>>(h2h, h2l, d3h, d3l, d3, out,
                                   nullptr, nullptr, B_, DIN, HID);
    }
}